// round 16
// baseline (speedup 1.0000x reference)
#include <cuda_runtime.h>
#include <cuda_bf16.h>
#include <math.h>
#include <stdint.h>

#define BB      4
#define NSEQ    512
#define DMODEL  512
#define NH      8
#define DK      64
#define TOK     (BB*NSEQ)      // 2048
#define DINNER  2048
#define LN_EPS  1e-6f
#define INV_T   0.125f         // 1/sqrt(64)

// ---------------- scratch ----------------------------------------------------
__device__ float g_v[BB*NH*NSEQ*DK];        // [b,h,n,d]
__device__ float g_Mmat[DK*4];              // combined rp matrix  M[d][p]
__device__ float g_cvec[DK];                // combined rp bias    c[d]
__device__ float g_heads[TOK*DMODEL];       // [b,n, h*dv]
__device__ float g_tmp1[TOK*DMODEL];
__device__ float g_ln1[TOK*DMODEL];
__device__ float g_ffh[TOK*DINNER];
__device__ float g_tmp2[TOK*DMODEL];

// bf16 fragment planes for the scores kernel (written by qkv3 epilogue)
__device__ uint4 g_kfrag[32*8*1024];        // 4 MB
__device__ uint4 g_qfrag[32*16*5*512];      // 21 MB

// ---------------- helpers ----------------------------------------------------
__device__ __forceinline__ float warp_sum(float v) {
    #pragma unroll
    for (int o = 16; o; o >>= 1) v += __shfl_xor_sync(0xffffffffu, v, o);
    return v;
}
__device__ __forceinline__ float warp_max(float v) {
    #pragma unroll
    for (int o = 16; o; o >>= 1) v = fmaxf(v, __shfl_xor_sync(0xffffffffu, v, o));
    return v;
}
__device__ __forceinline__ float to_tf32(float x) {
    uint32_t u;
    asm("cvt.rna.tf32.f32 %0, %1;" : "=r"(u) : "f"(x));
    return __uint_as_float(u);
}
__device__ __forceinline__ void mma_tf32(float (&c)[4], const uint32_t (&a)[4],
                                         const uint32_t (&b)[2]) {
    asm volatile(
        "mma.sync.aligned.m16n8k8.row.col.f32.tf32.tf32.f32 "
        "{%0,%1,%2,%3}, {%4,%5,%6,%7}, {%8,%9}, {%0,%1,%2,%3};\n"
        : "+f"(c[0]), "+f"(c[1]), "+f"(c[2]), "+f"(c[3])
        : "r"(a[0]), "r"(a[1]), "r"(a[2]), "r"(a[3]), "r"(b[0]), "r"(b[1]));
}
__device__ __forceinline__ void mma_bf16(float (&c)[4], const uint4& a,
                                         uint32_t b0, uint32_t b1) {
    asm volatile(
        "mma.sync.aligned.m16n8k16.row.col.f32.bf16.bf16.f32 "
        "{%0,%1,%2,%3}, {%4,%5,%6,%7}, {%8,%9}, {%0,%1,%2,%3};\n"
        : "+f"(c[0]), "+f"(c[1]), "+f"(c[2]), "+f"(c[3])
        : "r"(a.x), "r"(a.y), "r"(a.z), "r"(a.w), "r"(b0), "r"(b1));
}
__device__ __forceinline__ void mma_bf16r(float (&c)[4], const uint32_t (&a)[4],
                                          uint32_t b0, uint32_t b1) {
    asm volatile(
        "mma.sync.aligned.m16n8k16.row.col.f32.bf16.bf16.f32 "
        "{%0,%1,%2,%3}, {%4,%5,%6,%7}, {%8,%9}, {%0,%1,%2,%3};\n"
        : "+f"(c[0]), "+f"(c[1]), "+f"(c[2]), "+f"(c[3])
        : "r"(a[0]), "r"(a[1]), "r"(a[2]), "r"(a[3]), "r"(b0), "r"(b1));
}
__device__ __forceinline__ uint32_t pkbf2(float x0, float x1) {
    __nv_bfloat162 v = __floats2bfloat162_rn(x0, x1);
    return *reinterpret_cast<uint32_t*>(&v);
}
__device__ __forceinline__ float bfhi(float x) {
    return __bfloat162float(__float2bfloat16(x));
}

// ---------------- collapse rel-pos MLP: M = W2@W1, c = W2@b1 + b2 -----------
__global__ void rp_combine_kernel(const float* __restrict__ w1, const float* __restrict__ b1,
                                  const float* __restrict__ w2, const float* __restrict__ b2) {
    int d = threadIdx.x;
    if (d >= DK) return;
    float m0 = 0.f, m1 = 0.f, m2 = 0.f, m3 = 0.f, cc = 0.f;
    for (int k = 0; k < DK; k++) {
        float w = w2[d*DK + k];
        m0 = fmaf(w, w1[k*4+0], m0);
        m1 = fmaf(w, w1[k*4+1], m1);
        m2 = fmaf(w, w1[k*4+2], m2);
        m3 = fmaf(w, w1[k*4+3], m3);
        cc = fmaf(w, b1[k],      cc);
    }
    g_Mmat[d*4+0] = m0; g_Mmat[d*4+1] = m1;
    g_Mmat[d*4+2] = m2; g_Mmat[d*4+3] = m3;
    g_cvec[d] = cc + b2[d];
}

// ============================================================================
// QKV projection, 3-term compensated bf16 MMA. Epilogue writes:
//   q columns -> 5-channel Q' bf16 hi/lo fragments (g_qfrag)
//   k columns -> K bf16 hi/lo fragments (g_kfrag)
//   v columns -> g_v [b,h,n,d]
// (prep kernel eliminated; values identical — same fp32 register contents.)
// ============================================================================
__global__ __launch_bounds__(256)
void qkv3_kernel(const float* __restrict__ A,
                 const float* __restrict__ B0, const float* __restrict__ B1,
                 const float* __restrict__ B2, int colbase)
{
    const int K = DMODEL;
    __shared__ uint32_t Ah[2][8][136], Al[2][8][136];
    __shared__ uint32_t Bh[2][8][136], Bl[2][8][136];

    int tid  = threadIdx.x;
    int lane = tid & 31, warp = tid >> 5;
    int wm = warp >> 2, wn = warp & 3;
    int qr = lane >> 2, qc = lane & 3;
    int row0 = blockIdx.y << 7;
    int col0 = colbase + (blockIdx.x << 7);

    int wsel = col0 >> 9;                 // uniform per block: 0=q, 1=k, 2=v
    const float* Bw = (wsel == 0) ? B0 : ((wsel == 1) ? B1 : B2);
    const float* Bb = Bw + (size_t)(col0 & 511) * K;

    int ar = tid >> 1, aw = (tid & 1) << 2;
    const float* Ald = A + (size_t)(row0 + ar) * K + aw*2;
    const float* Bld = Bb + (size_t)ar * K + aw*2;

    float acc[4][4][4];
    #pragma unroll
    for (int mt = 0; mt < 4; mt++)
        #pragma unroll
        for (int nt = 0; nt < 4; nt++)
            #pragma unroll
            for (int c = 0; c < 4; c++) acc[mt][nt][c] = 0.f;

    float4 av0, av1, bv0, bv1;
    auto ldG = [&](int k0) {
        av0 = *(const float4*)(Ald + k0);
        av1 = *(const float4*)(Ald + k0 + 4);
        bv0 = *(const float4*)(Bld + k0);
        bv1 = *(const float4*)(Bld + k0 + 4);
    };
    auto stS = [&](int buf) {
        const float* ap0 = (const float*)&av0;
        const float* ap1 = (const float*)&av1;
        const float* bp0 = (const float*)&bv0;
        const float* bp1 = (const float*)&bv1;
        #pragma unroll
        for (int w = 0; w < 4; w++) {
            float x0 = (w < 2) ? ap0[2*w]   : ap1[2*w-4];
            float x1 = (w < 2) ? ap0[2*w+1] : ap1[2*w-3];
            float h0 = bfhi(x0), h1 = bfhi(x1);
            Ah[buf][aw+w][ar] = pkbf2(h0, h1);
            Al[buf][aw+w][ar] = pkbf2(x0 - h0, x1 - h1);
            float y0 = (w < 2) ? bp0[2*w]   : bp1[2*w-4];
            float y1 = (w < 2) ? bp0[2*w+1] : bp1[2*w-3];
            float g0 = bfhi(y0), g1 = bfhi(y1);
            Bh[buf][aw+w][ar] = pkbf2(g0, g1);
            Bl[buf][aw+w][ar] = pkbf2(y0 - g0, y1 - g1);
        }
    };
    auto compute = [&](int buf) {
        uint32_t afh[4][4], afl[4][4], bfh[4][2], bfl[4][2];
        #pragma unroll
        for (int mt = 0; mt < 4; mt++) {
            int mb = wm * 64 + mt * 16;
            afh[mt][0] = Ah[buf][qc  ][mb+qr  ];
            afh[mt][1] = Ah[buf][qc  ][mb+qr+8];
            afh[mt][2] = Ah[buf][qc+4][mb+qr  ];
            afh[mt][3] = Ah[buf][qc+4][mb+qr+8];
            afl[mt][0] = Al[buf][qc  ][mb+qr  ];
            afl[mt][1] = Al[buf][qc  ][mb+qr+8];
            afl[mt][2] = Al[buf][qc+4][mb+qr  ];
            afl[mt][3] = Al[buf][qc+4][mb+qr+8];
        }
        #pragma unroll
        for (int nt = 0; nt < 4; nt++) {
            int nb = wn * 32 + nt * 8;
            bfh[nt][0] = Bh[buf][qc  ][nb+qr];
            bfh[nt][1] = Bh[buf][qc+4][nb+qr];
            bfl[nt][0] = Bl[buf][qc  ][nb+qr];
            bfl[nt][1] = Bl[buf][qc+4][nb+qr];
        }
        #pragma unroll
        for (int mt = 0; mt < 4; mt++)
            #pragma unroll
            for (int nt = 0; nt < 4; nt++) {
                mma_bf16r(acc[mt][nt], afh[mt], bfh[nt][0], bfh[nt][1]);
                mma_bf16r(acc[mt][nt], afh[mt], bfl[nt][0], bfl[nt][1]);
                mma_bf16r(acc[mt][nt], afl[mt], bfh[nt][0], bfh[nt][1]);
            }
    };

    ldG(0);
    stS(0);
    __syncthreads();
    int buf = 0;
    for (int k0 = 16; k0 < K; k0 += 16) {
        ldG(k0);
        compute(buf);
        stS(buf ^ 1);
        __syncthreads();
        buf ^= 1;
    }
    compute(buf);

    // ---------------- epilogue: route by matrix ----------------
    if (wsel == 2) {
        // V: plain split-head store
        #pragma unroll
        for (int mt = 0; mt < 4; mt++) {
            int rbase = row0 + wm * 64 + mt * 16 + qr;
            #pragma unroll
            for (int nt = 0; nt < 4; nt++) {
                int c = col0 + wn * 32 + nt * 8 + 2 * qc;
                int cc = c & 511;
                int h = cc >> 6, d = cc & 63;
                #pragma unroll
                for (int hh = 0; hh < 2; hh++) {
                    int r = rbase + hh * 8;
                    int b = r >> 9, n = r & 511;
                    float2 v = make_float2(acc[mt][nt][2*hh], acc[mt][nt][2*hh+1]);
                    *(float2*)(g_v + ((((size_t)b * NH + h) * NSEQ) + n) * DK + d) = v;
                }
            }
        }
    } else if (wsel == 1) {
        // K: bf16 hi/lo fragment store
        #pragma unroll
        for (int nt = 0; nt < 4; nt++) {
            int c = col0 + wn * 32 + nt * 8 + 2 * qc;
            int cc = c & 511;
            int h = cc >> 6, d0 = cc & 63;
            int ks = d0 >> 4, kk = d0 & 15, qcc = (kk >> 1) & 3, khalf = kk >> 3;
            #pragma unroll
            for (int mt = 0; mt < 4; mt++) {
                int rbase = row0 + wm * 64 + mt * 16 + qr;
                #pragma unroll
                for (int hh = 0; hh < 2; hh++) {
                    int r = rbase + hh * 8;
                    int b = r >> 9, n = r & 511;
                    int z = b * NH + h;
                    int jg = n >> 6, jl = n & 63;
                    int qrj = jl & 7, jhalf = (jl >> 3) & 1, mg = jl >> 4;
                    uint32_t* dst = reinterpret_cast<uint32_t*>(g_kfrag)
                                  + (size_t)(z*8 + jg)*4096;
                    int base = ((mg*4 + ks)*32 + qrj*4 + qcc)*4 + (jhalf + 2*khalf);
                    float vx = acc[mt][nt][2*hh], vy = acc[mt][nt][2*hh+1];
                    float h0 = bfhi(vx), h1 = bfhi(vy);
                    dst[base]        = pkbf2(h0, h1);
                    dst[2048 + base] = pkbf2(vx - h0, vy - h1);
                }
            }
        }
    } else {
        // Q: 5-channel Q' bf16 hi/lo fragment store
        #pragma unroll
        for (int nt = 0; nt < 4; nt++) {
            int c = col0 + wn * 32 + nt * 8 + 2 * qc;
            int cc = c & 511;
            int h = cc >> 6, d0 = cc & 63;
            int ks = d0 >> 4, kk = d0 & 15, qcc = (kk >> 1) & 3, khalf = kk >> 3;
            float w0[5], w1[5];
            #pragma unroll
            for (int p = 0; p < 4; p++) {
                w0[p] = g_Mmat[d0*4 + p];
                w1[p] = g_Mmat[(d0+1)*4 + p];
            }
            w0[4] = g_cvec[d0];
            w1[4] = g_cvec[d0+1];
            #pragma unroll
            for (int mt = 0; mt < 4; mt++) {
                int rbase = row0 + wm * 64 + mt * 16 + qr;
                #pragma unroll
                for (int hh = 0; hh < 2; hh++) {
                    int r = rbase + hh * 8;
                    int b = r >> 9, n = r & 511;
                    int z = b * NH + h;
                    int ig = n >> 5, iin = n & 31;
                    int qri = iin & 7, ng = iin >> 3;
                    uint32_t* bd0 = reinterpret_cast<uint32_t*>(g_qfrag)
                                  + (size_t)(z*16 + ig)*5*2048;
                    int fb = ((ng*4 + ks)*32 + qri*4 + qcc)*4;
                    float vx = acc[mt][nt][2*hh], vy = acc[mt][nt][2*hh+1];
                    #pragma unroll
                    for (int ch = 0; ch < 5; ch++) {
                        float p0 = vx * w0[ch];
                        float p1 = vy * w1[ch];
                        float h0 = bfhi(p0), h1 = bfhi(p1);
                        uint32_t* bd = bd0 + ch*2048;
                        bd[fb + khalf]     = pkbf2(h0, h1);
                        bd[fb + 2 + khalf] = pkbf2(p0 - h0, p1 - h1);
                    }
                }
            }
        }
    }
}

// ============================================================================
// Legacy TF32 GEMM — kept ONLY for AV (MAP=2, BTRANS=false, TN=64).
// ============================================================================
template<int TN, int MAP, bool BTRANS, bool BIAS, bool RELU, bool RESID>
__global__ __launch_bounds__(256)
void tgemm_kernel(const float* __restrict__ A, const float* __restrict__ B0,
                  const float* __restrict__ bias, const float* __restrict__ resid,
                  float* __restrict__ C, int N, int K,
                  size_t strideA, size_t strideB)
{
    constexpr int NT   = TN / 32;
    constexpr int WN   = TN / 4;
    constexpr int BPAD = (TN == 128) ? 136 : 72;

    __shared__ __align__(16) float As[2][16][136];
    __shared__ __align__(16) float Bs[2][16][BPAD];

    int tid  = threadIdx.x;
    int lane = tid & 31, warp = tid >> 5;
    int wm = warp >> 2, wn = warp & 3;
    int qr = lane >> 2, qc = lane & 3;
    int row0 = blockIdx.y << 7;
    int col0 = blockIdx.x * TN;
    int z    = blockIdx.z;

    const float* Ab = A + (size_t)z * strideA;
    const float* Bb = BTRANS ? (B0 + (size_t)col0 * K)
                             : (B0 + (size_t)z * strideB + col0);

    int ar = tid >> 2, ak = (tid & 3) << 2;
    const float* Ald = Ab + (size_t)(row0 + ar) * K + ak;
    const float* Bld_t = Bb + (size_t)ar * K + ak;
    int bkr = tid >> 4, bn4 = (tid & 15) << 2;
    const float* Bld_n = Bb + (size_t)bkr * N + bn4;

    float acc[4][NT][4];
    #pragma unroll
    for (int mt = 0; mt < 4; mt++)
        #pragma unroll
        for (int nt = 0; nt < NT; nt++)
            #pragma unroll
            for (int c = 0; c < 4; c++) acc[mt][nt][c] = 0.f;

    float4 av[2], bv[2];
    auto ldG = [&](int k0) {
        av[0] = *(const float4*)(Ald + k0);
        av[1] = *(const float4*)(Ald + (size_t)64 * K + k0);
        if (BTRANS) {
            bv[0] = *(const float4*)(Bld_t + k0);
            if (TN == 128) bv[1] = *(const float4*)(Bld_t + (size_t)64 * K + k0);
        } else {
            bv[0] = *(const float4*)(Bld_n + (size_t)k0 * N);
        }
    };
    auto stS = [&](int buf) {
        #pragma unroll
        for (int h = 0; h < 2; h++) {
            int r = ar + h * 64;
            As[buf][ak+0][r] = to_tf32(((const float*)&av[h])[0]);
            As[buf][ak+1][r] = to_tf32(((const float*)&av[h])[1]);
            As[buf][ak+2][r] = to_tf32(((const float*)&av[h])[2]);
            As[buf][ak+3][r] = to_tf32(((const float*)&av[h])[3]);
        }
        if (BTRANS) {
            #pragma unroll
            for (int h = 0; h < (TN == 128 ? 2 : 1); h++) {
                int r = ar + h * 64;
                if (TN == 128 || r < TN) {
                    Bs[buf][ak+0][r] = to_tf32(((const float*)&bv[h])[0]);
                    Bs[buf][ak+1][r] = to_tf32(((const float*)&bv[h])[1]);
                    Bs[buf][ak+2][r] = to_tf32(((const float*)&bv[h])[2]);
                    Bs[buf][ak+3][r] = to_tf32(((const float*)&bv[h])[3]);
                }
            }
        } else {
            float4 t = make_float4(to_tf32(bv[0].x), to_tf32(bv[0].y),
                                   to_tf32(bv[0].z), to_tf32(bv[0].w));
            *(float4*)&Bs[buf][bkr][bn4] = t;
        }
    };
    auto compute = [&](int buf) {
        #pragma unroll
        for (int ks = 0; ks < 2; ks++) {
            int kb = ks * 8;
            uint32_t af[4][4], bf[NT][2];
            #pragma unroll
            for (int mt = 0; mt < 4; mt++) {
                int mb = wm * 64 + mt * 16;
                af[mt][0] = __float_as_uint(As[buf][kb+qc  ][mb+qr  ]);
                af[mt][1] = __float_as_uint(As[buf][kb+qc  ][mb+qr+8]);
                af[mt][2] = __float_as_uint(As[buf][kb+qc+4][mb+qr  ]);
                af[mt][3] = __float_as_uint(As[buf][kb+qc+4][mb+qr+8]);
            }
            #pragma unroll
            for (int nt = 0; nt < NT; nt++) {
                int nb = wn * WN + nt * 8;
                bf[nt][0] = __float_as_uint(Bs[buf][kb+qc  ][nb+qr]);
                bf[nt][1] = __float_as_uint(Bs[buf][kb+qc+4][nb+qr]);
            }
            #pragma unroll
            for (int mt = 0; mt < 4; mt++)
                #pragma unroll
                for (int nt = 0; nt < NT; nt++)
                    mma_tf32(acc[mt][nt], af[mt], bf[nt]);
        }
    };

    ldG(0);
    stS(0);
    __syncthreads();
    int buf = 0;
    for (int k0 = 16; k0 < K; k0 += 16) {
        ldG(k0);
        compute(buf);
        stS(buf ^ 1);
        __syncthreads();
        buf ^= 1;
    }
    compute(buf);

    #pragma unroll
    for (int mt = 0; mt < 4; mt++) {
        int rbase = row0 + wm * 64 + mt * 16 + qr;
        #pragma unroll
        for (int nt = 0; nt < NT; nt++) {
            int cg = col0 + wn * WN + nt * 8 + 2 * qc;
            #pragma unroll
            for (int hh = 0; hh < 2; hh++) {
                int r = rbase + hh * 8;
                float2 v = make_float2(acc[mt][nt][2*hh], acc[mt][nt][2*hh+1]);
                if (BIAS) { v.x += bias[cg]; v.y += bias[cg+1]; }
                if (RESID) {
                    const float2 rz = *(const float2*)(resid + (size_t)r * N + cg);
                    v.x += rz.x; v.y += rz.y;
                }
                if (RELU) { v.x = fmaxf(v.x, 0.f); v.y = fmaxf(v.y, 0.f); }
                if (MAP == 0) {
                    *(float2*)(C + (size_t)r * N + cg) = v;
                } else {
                    int b = z >> 3, h2 = z & 7;
                    *(float2*)(g_heads + ((size_t)(b * NSEQ) + r) * DMODEL + h2 * DK + cg) = v;
                }
            }
        }
    }
}

// ============================================================================
// tgemm_bt: C = A @ B^T (tf32) with PRE-SWIZZLED fragments in smem.
// Inner loop per warp-k16: 12 LDS.128 + 32 mma (was 48 scalar LDS).
// Used for fc, FFN1, FFN2. Same tf32 values & accumulation order as before.
// ============================================================================
template<int TN, bool BIAS, bool RELU, bool RESID>
__global__ __launch_bounds__(256)
void tgemm_bt_kernel(const float* __restrict__ A, const float* __restrict__ B0,
                     const float* __restrict__ bias, const float* __restrict__ resid,
                     float* __restrict__ C, int N, int K)
{
    constexpr int NT = TN / 32;
    constexpr int WN = TN / 4;

    __shared__ __align__(16) uint4 Asw[2][512];        // [(g*2+ks)*32+lane]
    __shared__ __align__(16) uint4 Bsw[2][TN*4];       // [ng*32+lane], 2 ks packed

    int tid  = threadIdx.x;
    int lane = tid & 31, warp = tid >> 5;
    int wm = warp >> 2, wn = warp & 3;
    int qr = lane >> 2, qc = lane & 3;
    int row0 = blockIdx.y << 7;
    int col0 = blockIdx.x * TN;

    int ar = tid >> 2, ak = (tid & 3) << 2;            // ar 0..63, ak {0,4,8,12}
    const float* Ald = A + (size_t)(row0 + ar) * K + ak;
    const float* Bld = B0 + (size_t)(col0 + ar) * K + ak;

    int ksw = ak >> 3;            // k-step of this loader chunk
    int khw = (ak >> 2) & 1;      // k-half within k8

    float acc[4][NT][4];
    #pragma unroll
    for (int mt = 0; mt < 4; mt++)
        #pragma unroll
        for (int nt = 0; nt < NT; nt++)
            #pragma unroll
            for (int c = 0; c < 4; c++) acc[mt][nt][c] = 0.f;

    float4 av0, av1, bv0, bv1;
    auto ldG = [&](int k0) {
        av0 = *(const float4*)(Ald + k0);
        av1 = *(const float4*)(Ald + (size_t)64 * K + k0);
        bv0 = *(const float4*)(Bld + k0);
        if (TN == 128) bv1 = *(const float4*)(Bld + (size_t)64 * K + k0);
    };
    auto stS = [&](int buf) {
        uint32_t* Aw = reinterpret_cast<uint32_t*>(&Asw[buf][0]);
        uint32_t* Bw = reinterpret_cast<uint32_t*>(&Bsw[buf][0]);
        #pragma unroll
        for (int hfl = 0; hfl < 2; hfl++) {
            int r = ar + 64*hfl;
            const float* src = (hfl == 0) ? (const float*)&av0 : (const float*)&av1;
            int g = r >> 4, qrj = r & 7, rh = (r >> 3) & 1;
            int w = rh + 2*khw;
            int lb = ((g*2 + ksw)*32 + qrj*4);
            #pragma unroll
            for (int e = 0; e < 4; e++)
                Aw[(lb + e)*4 + w] = __float_as_uint(to_tf32(src[e]));
        }
        int wB = khw + 2*ksw;
        #pragma unroll
        for (int hfl = 0; hfl < (TN == 128 ? 2 : 1); hfl++) {
            int r = ar + 64*hfl;
            const float* src = (hfl == 0) ? (const float*)&bv0 : (const float*)&bv1;
            int ng = r >> 3, qrb = r & 7;
            int lb = ng*32 + qrb*4;
            #pragma unroll
            for (int e = 0; e < 4; e++)
                Bw[(lb + e)*4 + wB] = __float_as_uint(to_tf32(src[e]));
        }
    };
    auto compute = [&](int buf) {
        uint4 af[4][2];
        #pragma unroll
        for (int mt = 0; mt < 4; mt++) {
            int mg = wm*4 + mt;
            af[mt][0] = Asw[buf][(mg*2 + 0)*32 + lane];
            af[mt][1] = Asw[buf][(mg*2 + 1)*32 + lane];
        }
        uint4 bq[NT];
        #pragma unroll
        for (int nt = 0; nt < NT; nt++)
            bq[nt] = Bsw[buf][(wn*NT + nt)*32 + lane];
        #pragma unroll
        for (int ks = 0; ks < 2; ks++)
            #pragma unroll
            for (int mt = 0; mt < 4; mt++)
                #pragma unroll
                for (int nt = 0; nt < NT; nt++) {
                    uint32_t b2[2];
                    b2[0] = ks ? bq[nt].z : bq[nt].x;
                    b2[1] = ks ? bq[nt].w : bq[nt].y;
                    mma_tf32(acc[mt][nt],
                             *reinterpret_cast<const uint32_t(*)[4]>(&af[mt][ks]), b2);
                }
    };

    ldG(0);
    stS(0);
    __syncthreads();
    int buf = 0;
    for (int k0 = 16; k0 < K; k0 += 16) {
        ldG(k0);
        compute(buf);
        stS(buf ^ 1);
        __syncthreads();
        buf ^= 1;
    }
    compute(buf);

    #pragma unroll
    for (int mt = 0; mt < 4; mt++) {
        int rbase = row0 + wm * 64 + mt * 16 + qr;
        #pragma unroll
        for (int nt = 0; nt < NT; nt++) {
            int cg = col0 + wn * WN + nt * 8 + 2 * qc;
            #pragma unroll
            for (int hh = 0; hh < 2; hh++) {
                int r = rbase + hh * 8;
                float2 v = make_float2(acc[mt][nt][2*hh], acc[mt][nt][2*hh+1]);
                if (BIAS) { v.x += bias[cg]; v.y += bias[cg+1]; }
                if (RESID) {
                    const float2 rz = *(const float2*)(resid + (size_t)r * N + cg);
                    v.x += rz.x; v.y += rz.y;
                }
                if (RELU) { v.x = fmaxf(v.x, 0.f); v.y = fmaxf(v.y, 0.f); }
                *(float2*)(C + (size_t)r * N + cg) = v;
            }
        }
    }
}

// ============================================================================
// scores v6: all 8 heads per block (pos in registers); bf16 3-term m16n8k16.
// ============================================================================
__global__ __launch_bounds__(256)
void scores_tc_kernel(const float* __restrict__ pos, float* __restrict__ attn)
{
    int tid  = threadIdx.x;
    int lane = tid & 31, warp = tid >> 5;
    int wm = warp >> 2, wn = warp & 3;
    int qr = lane >> 2, qc = lane & 3;
    int ig = blockIdx.x, jg = blockIdx.y, bbx = blockIdx.z;
    int i0 = ig << 5, j0 = jg << 6;
    int colb = i0 + wn*8 + 2*qc;

    float4 pr[2][2][2];
    #pragma unroll
    for (int mt = 0; mt < 2; mt++)
        #pragma unroll
        for (int hf = 0; hf < 2; hf++) {
            int row = j0 + wm*32 + mt*16 + qr + 8*hf;
            const float* pp = pos + (((size_t)(bbx*NSEQ + row))*NSEQ + colb)*4;
            pr[mt][hf][0] = *(const float4*)pp;
            pr[mt][hf][1] = *(const float4*)(pp + 4);
        }

    #pragma unroll 1
    for (int h = 0; h < NH; h++) {
        int z = bbx*NH + h;
        const uint4* Af = g_kfrag + (size_t)(z*8 + jg)*1024;
        const uint4* Bf = g_qfrag + (size_t)(z*16 + ig)*2560 + wn*128 + lane;

        float acc[5][2][4];
        #pragma unroll
        for (int ch = 0; ch < 5; ch++)
            #pragma unroll
            for (int mt = 0; mt < 2; mt++)
                #pragma unroll
                for (int c = 0; c < 4; c++) acc[ch][mt][c] = 0.f;

        #pragma unroll
        for (int ks = 0; ks < 4; ks++) {
            uint4 ah[2], al[2];
            #pragma unroll
            for (int mt = 0; mt < 2; mt++) {
                int fi = (wm*2 + mt)*128 + ks*32 + lane;
                ah[mt] = __ldg(&Af[fi]);
                al[mt] = __ldg(&Af[512 + fi]);
            }
            #pragma unroll
            for (int ch = 0; ch < 5; ch++) {
                uint4 bq = __ldg(&Bf[ch*512 + ks*32]);
                #pragma unroll
                for (int mt = 0; mt < 2; mt++) {
                    mma_bf16(acc[ch][mt], ah[mt], bq.x, bq.y);
                    mma_bf16(acc[ch][mt], ah[mt], bq.z, bq.w);
                    mma_bf16(acc[ch][mt], al[mt], bq.x, bq.y);
                }
            }
        }

        #pragma unroll
        for (int mt = 0; mt < 2; mt++)
            #pragma unroll
            for (int hf = 0; hf < 2; hf++) {
                int row = j0 + wm*32 + mt*16 + qr + 8*hf;
                float4 p0 = pr[mt][hf][0];
                float4 p1 = pr[mt][hf][1];
                int c = 2*hf;
                float s0 = acc[4][mt][c]
                         + p0.x*acc[0][mt][c] + p0.y*acc[1][mt][c]
                         + p0.z*acc[2][mt][c] + p0.w*acc[3][mt][c];
                float s1 = acc[4][mt][c+1]
                         + p1.x*acc[0][mt][c+1] + p1.y*acc[1][mt][c+1]
                         + p1.z*acc[2][mt][c+1] + p1.w*acc[3][mt][c+1];
                *(float2*)(attn + ((size_t)z*NSEQ + row)*NSEQ + colb) =
                    make_float2(s0*INV_T, s1*INV_T);
            }
    }
}

// ---------------- softmax: warp per row, 8 rows per block, float4 -----------
__global__ __launch_bounds__(256)
void softmax_kernel(float* __restrict__ attn)
{
    int warp = threadIdx.x >> 5, lane = threadIdx.x & 31;
    size_t row = (size_t)blockIdx.x * 8 + warp;
    float4* p = reinterpret_cast<float4*>(attn + row * NSEQ);

    float4 v[4];
    #pragma unroll
    for (int u = 0; u < 4; u++) v[u] = p[lane + 32*u];

    float m = -1e30f;
    #pragma unroll
    for (int u = 0; u < 4; u++)
        m = fmaxf(m, fmaxf(fmaxf(v[u].x, v[u].y), fmaxf(v[u].z, v[u].w)));
    m = warp_max(m);

    float s = 0.f;
    #pragma unroll
    for (int u = 0; u < 4; u++) {
        v[u].x = __expf(v[u].x - m); v[u].y = __expf(v[u].y - m);
        v[u].z = __expf(v[u].z - m); v[u].w = __expf(v[u].w - m);
        s += v[u].x + v[u].y + v[u].z + v[u].w;
    }
    s = warp_sum(s);
    float inv = 1.0f / s;
    #pragma unroll
    for (int u = 0; u < 4; u++) {
        v[u].x *= inv; v[u].y *= inv; v[u].z *= inv; v[u].w *= inv;
        p[lane + 32*u] = v[u];
    }
}

// ---------------- layer norm (one token per block) ---------------------------
__global__ __launch_bounds__(256)
void layernorm_kernel(const float* __restrict__ x, const float* __restrict__ gam,
                      const float* __restrict__ bet, float* __restrict__ out)
{
    int t = blockIdx.x, tid = threadIdx.x;
    const float* xr = x + (size_t)t * DMODEL;
    __shared__ float red[8];

    float a0 = xr[tid], a1 = xr[tid + 256];
    float s = warp_sum(a0 + a1);
    if ((tid & 31) == 0) red[tid >> 5] = s;
    __syncthreads();
    s = red[0];
    #pragma unroll
    for (int w = 1; w < 8; w++) s += red[w];
    float mu = s * (1.0f / DMODEL);
    float d0 = a0 - mu, d1 = a1 - mu;
    __syncthreads();

    float q = warp_sum(d0*d0 + d1*d1);
    if ((tid & 31) == 0) red[tid >> 5] = q;
    __syncthreads();
    q = red[0];
    #pragma unroll
    for (int w = 1; w < 8; w++) q += red[w];
    float inv = rsqrtf(q * (1.0f / DMODEL) + LN_EPS);

    float* orow = out + (size_t)t * DMODEL;
    orow[tid]       = d0 * inv * gam[tid]       + bet[tid];
    orow[tid + 256] = d1 * inv * gam[tid + 256] + bet[tid + 256];
}

// ---------------- launch -----------------------------------------------------
extern "C" void kernel_launch(void* const* d_in, const int* in_sizes, int n_in,
                              void* d_out, int out_size)
{
    (void)in_sizes; (void)n_in; (void)out_size;
    const float* enc    = (const float*)d_in[0];
    const float* pos    = (const float*)d_in[1];
    const float* w_qs   = (const float*)d_in[2];
    const float* w_ks   = (const float*)d_in[3];
    const float* w_vs   = (const float*)d_in[4];
    const float* w_fc   = (const float*)d_in[5];
    const float* rp_w1  = (const float*)d_in[6];
    const float* rp_b1  = (const float*)d_in[7];
    const float* rp_w2  = (const float*)d_in[8];
    const float* rp_b2  = (const float*)d_in[9];
    const float* ln1_g  = (const float*)d_in[10];
    const float* ln1_b  = (const float*)d_in[11];
    const float* ln2_g  = (const float*)d_in[12];
    const float* ln2_b  = (const float*)d_in[13];
    const float* ffn_w1 = (const float*)d_in[14];
    const float* ffn_b1 = (const float*)d_in[15];
    const float* ffn_w2 = (const float*)d_in[16];
    const float* ffn_b2 = (const float*)d_in[17];

    float* out2 = (float*)d_out;                          // [4,512,512]
    float* attn = out2 + (size_t)TOK * DMODEL;            // [4,8,512,512]

    float *pv, *pheads, *ptmp1, *pln1, *pffh, *ptmp2;
    cudaGetSymbolAddress((void**)&pv,     g_v);
    cudaGetSymbolAddress((void**)&pheads, g_heads);
    cudaGetSymbolAddress((void**)&ptmp1,  g_tmp1);
    cudaGetSymbolAddress((void**)&pln1,   g_ln1);
    cudaGetSymbolAddress((void**)&pffh,   g_ffh);
    cudaGetSymbolAddress((void**)&ptmp2,  g_tmp2);

    // 1) collapse rel-pos MLP
    rp_combine_kernel<<<1, 64>>>(rp_w1, rp_b1, rp_w2, rp_b2);

    // 2+3) QKV projection; epilogue writes fragments (prep eliminated)
    {
        dim3 g(6, TOK/128, 1);
        qkv3_kernel<<<g, 256>>>(enc, w_qs, w_ks, w_vs, 0);
        qkv3_kernel<<<g, 256>>>(enc, w_qs, w_ks, w_vs, 768);
    }

    // 4) relative-position attention logits (slot 4 -> profiled)
    {
        dim3 g(NSEQ/32, NSEQ/64, BB);      // 512 blocks
        scores_tc_kernel<<<g, 256>>>(pos, attn);
    }

    // 5) softmax in place (warp per row)
    softmax_kernel<<<BB*NH*NSEQ/8, 256>>>(attn);

    // 6) AV (tf32 legacy): per (b,h): P @ V -> g_heads
    {
        dim3 g(1, NSEQ/128, BB*NH);
        tgemm_kernel<64, 2, false, false, false, false><<<g, 256>>>(
            attn, pv, nullptr, nullptr, nullptr,
            DK, NSEQ, (size_t)NSEQ*NSEQ, (size_t)NSEQ*DK);
    }

    // 7) fc + residual(enc) -> g_tmp1 ; LN1
    {
        dim3 g(DMODEL/64, TOK/128, 1);
        tgemm_bt_kernel<64, false, false, true><<<g, 256>>>(
            pheads, w_fc, nullptr, enc, ptmp1, DMODEL, DMODEL);
    }
    layernorm_kernel<<<TOK, 256>>>(ptmp1, ln1_g, ln1_b, pln1);

    // 8) FFN1: relu(ln1 @ W1^T + b1) -> g_ffh
    {
        dim3 g(DINNER/128, TOK/128, 1);
        tgemm_bt_kernel<128, true, true, false><<<g, 256>>>(
            pln1, ffn_w1, ffn_b1, nullptr, pffh, DINNER, DMODEL);
    }

    // 9) FFN2: ffh @ W2^T + b2 + ln1 -> g_tmp2
    {
        dim3 g(DMODEL/64, TOK/128, 1);
        tgemm_bt_kernel<64, true, false, true><<<g, 256>>>(
            pffh, ffn_w2, ffn_b2, pln1, ptmp2, DMODEL, DINNER);
    }

    // 10) LN2 -> out2
    layernorm_kernel<<<TOK, 256>>>(ptmp2, ln2_g, ln2_b, out2);
}

// round 17
// speedup vs baseline: 1.0338x; 1.0338x over previous
#include <cuda_runtime.h>
#include <cuda_bf16.h>
#include <math.h>
#include <stdint.h>

#define BB      4
#define NSEQ    512
#define DMODEL  512
#define NH      8
#define DK      64
#define TOK     (BB*NSEQ)      // 2048
#define DINNER  2048
#define LN_EPS  1e-6f
#define INV_T   0.125f         // 1/sqrt(64)

// ---------------- scratch ----------------------------------------------------
__device__ float g_v[BB*NH*NSEQ*DK];        // [b,h,n,d]
__device__ float g_Mmat[DK*4];              // combined rp matrix  M[d][p]
__device__ float g_cvec[DK];                // combined rp bias    c[d]
__device__ float g_heads[TOK*DMODEL];       // [b,n, h*dv]
__device__ float g_tmp1[TOK*DMODEL];
__device__ float g_ln1[TOK*DMODEL];
__device__ float g_ffh[TOK*DINNER];
__device__ float g_tmp2[TOK*DMODEL];

// bf16 fragment planes for the scores kernel (written by qkv3 epilogue)
__device__ uint4 g_kfrag[32*8*1024];        // 4 MB
__device__ uint4 g_qfrag[32*16*5*512];      // 21 MB

// ---------------- helpers ----------------------------------------------------
__device__ __forceinline__ float warp_sum(float v) {
    #pragma unroll
    for (int o = 16; o; o >>= 1) v += __shfl_xor_sync(0xffffffffu, v, o);
    return v;
}
__device__ __forceinline__ float warp_max(float v) {
    #pragma unroll
    for (int o = 16; o; o >>= 1) v = fmaxf(v, __shfl_xor_sync(0xffffffffu, v, o));
    return v;
}
__device__ __forceinline__ float to_tf32(float x) {
    uint32_t u;
    asm("cvt.rna.tf32.f32 %0, %1;" : "=r"(u) : "f"(x));
    return __uint_as_float(u);
}
__device__ __forceinline__ void mma_tf32(float (&c)[4], const uint32_t (&a)[4],
                                         const uint32_t (&b)[2]) {
    asm volatile(
        "mma.sync.aligned.m16n8k8.row.col.f32.tf32.tf32.f32 "
        "{%0,%1,%2,%3}, {%4,%5,%6,%7}, {%8,%9}, {%0,%1,%2,%3};\n"
        : "+f"(c[0]), "+f"(c[1]), "+f"(c[2]), "+f"(c[3])
        : "r"(a[0]), "r"(a[1]), "r"(a[2]), "r"(a[3]), "r"(b[0]), "r"(b[1]));
}
__device__ __forceinline__ void mma_bf16(float (&c)[4], const uint4& a,
                                         uint32_t b0, uint32_t b1) {
    asm volatile(
        "mma.sync.aligned.m16n8k16.row.col.f32.bf16.bf16.f32 "
        "{%0,%1,%2,%3}, {%4,%5,%6,%7}, {%8,%9}, {%0,%1,%2,%3};\n"
        : "+f"(c[0]), "+f"(c[1]), "+f"(c[2]), "+f"(c[3])
        : "r"(a.x), "r"(a.y), "r"(a.z), "r"(a.w), "r"(b0), "r"(b1));
}
__device__ __forceinline__ void mma_bf16r(float (&c)[4], const uint32_t (&a)[4],
                                          uint32_t b0, uint32_t b1) {
    asm volatile(
        "mma.sync.aligned.m16n8k16.row.col.f32.bf16.bf16.f32 "
        "{%0,%1,%2,%3}, {%4,%5,%6,%7}, {%8,%9}, {%0,%1,%2,%3};\n"
        : "+f"(c[0]), "+f"(c[1]), "+f"(c[2]), "+f"(c[3])
        : "r"(a[0]), "r"(a[1]), "r"(a[2]), "r"(a[3]), "r"(b0), "r"(b1));
}
__device__ __forceinline__ uint32_t pkbf2(float x0, float x1) {
    __nv_bfloat162 v = __floats2bfloat162_rn(x0, x1);
    return *reinterpret_cast<uint32_t*>(&v);
}
__device__ __forceinline__ float bfhi(float x) {
    return __bfloat162float(__float2bfloat16(x));
}

// ---------------- collapse rel-pos MLP: M = W2@W1, c = W2@b1 + b2 -----------
__global__ void rp_combine_kernel(const float* __restrict__ w1, const float* __restrict__ b1,
                                  const float* __restrict__ w2, const float* __restrict__ b2) {
    int d = threadIdx.x;
    if (d >= DK) return;
    float m0 = 0.f, m1 = 0.f, m2 = 0.f, m3 = 0.f, cc = 0.f;
    for (int k = 0; k < DK; k++) {
        float w = w2[d*DK + k];
        m0 = fmaf(w, w1[k*4+0], m0);
        m1 = fmaf(w, w1[k*4+1], m1);
        m2 = fmaf(w, w1[k*4+2], m2);
        m3 = fmaf(w, w1[k*4+3], m3);
        cc = fmaf(w, b1[k],      cc);
    }
    g_Mmat[d*4+0] = m0; g_Mmat[d*4+1] = m1;
    g_Mmat[d*4+2] = m2; g_Mmat[d*4+3] = m3;
    g_cvec[d] = cc + b2[d];
}

// ============================================================================
// QKV projection, 3-term compensated bf16 MMA. Epilogue writes:
//   q columns -> 5-channel Q' bf16 hi/lo fragments (g_qfrag)
//   k columns -> K bf16 hi/lo fragments (g_kfrag)
//   v columns -> g_v [b,h,n,d]
// ============================================================================
__global__ __launch_bounds__(256)
void qkv3_kernel(const float* __restrict__ A,
                 const float* __restrict__ B0, const float* __restrict__ B1,
                 const float* __restrict__ B2, int colbase)
{
    const int K = DMODEL;
    __shared__ uint32_t Ah[2][8][136], Al[2][8][136];
    __shared__ uint32_t Bh[2][8][136], Bl[2][8][136];

    int tid  = threadIdx.x;
    int lane = tid & 31, warp = tid >> 5;
    int wm = warp >> 2, wn = warp & 3;
    int qr = lane >> 2, qc = lane & 3;
    int row0 = blockIdx.y << 7;
    int col0 = colbase + (blockIdx.x << 7);

    int wsel = col0 >> 9;                 // uniform per block: 0=q, 1=k, 2=v
    const float* Bw = (wsel == 0) ? B0 : ((wsel == 1) ? B1 : B2);
    const float* Bb = Bw + (size_t)(col0 & 511) * K;

    int ar = tid >> 1, aw = (tid & 1) << 2;
    const float* Ald = A + (size_t)(row0 + ar) * K + aw*2;
    const float* Bld = Bb + (size_t)ar * K + aw*2;

    float acc[4][4][4];
    #pragma unroll
    for (int mt = 0; mt < 4; mt++)
        #pragma unroll
        for (int nt = 0; nt < 4; nt++)
            #pragma unroll
            for (int c = 0; c < 4; c++) acc[mt][nt][c] = 0.f;

    float4 av0, av1, bv0, bv1;
    auto ldG = [&](int k0) {
        av0 = *(const float4*)(Ald + k0);
        av1 = *(const float4*)(Ald + k0 + 4);
        bv0 = *(const float4*)(Bld + k0);
        bv1 = *(const float4*)(Bld + k0 + 4);
    };
    auto stS = [&](int buf) {
        const float* ap0 = (const float*)&av0;
        const float* ap1 = (const float*)&av1;
        const float* bp0 = (const float*)&bv0;
        const float* bp1 = (const float*)&bv1;
        #pragma unroll
        for (int w = 0; w < 4; w++) {
            float x0 = (w < 2) ? ap0[2*w]   : ap1[2*w-4];
            float x1 = (w < 2) ? ap0[2*w+1] : ap1[2*w-3];
            float h0 = bfhi(x0), h1 = bfhi(x1);
            Ah[buf][aw+w][ar] = pkbf2(h0, h1);
            Al[buf][aw+w][ar] = pkbf2(x0 - h0, x1 - h1);
            float y0 = (w < 2) ? bp0[2*w]   : bp1[2*w-4];
            float y1 = (w < 2) ? bp0[2*w+1] : bp1[2*w-3];
            float g0 = bfhi(y0), g1 = bfhi(y1);
            Bh[buf][aw+w][ar] = pkbf2(g0, g1);
            Bl[buf][aw+w][ar] = pkbf2(y0 - g0, y1 - g1);
        }
    };
    auto compute = [&](int buf) {
        uint32_t afh[4][4], afl[4][4], bfh[4][2], bfl[4][2];
        #pragma unroll
        for (int mt = 0; mt < 4; mt++) {
            int mb = wm * 64 + mt * 16;
            afh[mt][0] = Ah[buf][qc  ][mb+qr  ];
            afh[mt][1] = Ah[buf][qc  ][mb+qr+8];
            afh[mt][2] = Ah[buf][qc+4][mb+qr  ];
            afh[mt][3] = Ah[buf][qc+4][mb+qr+8];
            afl[mt][0] = Al[buf][qc  ][mb+qr  ];
            afl[mt][1] = Al[buf][qc  ][mb+qr+8];
            afl[mt][2] = Al[buf][qc+4][mb+qr  ];
            afl[mt][3] = Al[buf][qc+4][mb+qr+8];
        }
        #pragma unroll
        for (int nt = 0; nt < 4; nt++) {
            int nb = wn * 32 + nt * 8;
            bfh[nt][0] = Bh[buf][qc  ][nb+qr];
            bfh[nt][1] = Bh[buf][qc+4][nb+qr];
            bfl[nt][0] = Bl[buf][qc  ][nb+qr];
            bfl[nt][1] = Bl[buf][qc+4][nb+qr];
        }
        #pragma unroll
        for (int mt = 0; mt < 4; mt++)
            #pragma unroll
            for (int nt = 0; nt < 4; nt++) {
                mma_bf16r(acc[mt][nt], afh[mt], bfh[nt][0], bfh[nt][1]);
                mma_bf16r(acc[mt][nt], afh[mt], bfl[nt][0], bfl[nt][1]);
                mma_bf16r(acc[mt][nt], afl[mt], bfh[nt][0], bfh[nt][1]);
            }
    };

    ldG(0);
    stS(0);
    __syncthreads();
    int buf = 0;
    for (int k0 = 16; k0 < K; k0 += 16) {
        ldG(k0);
        compute(buf);
        stS(buf ^ 1);
        __syncthreads();
        buf ^= 1;
    }
    compute(buf);

    // ---------------- epilogue: route by matrix ----------------
    if (wsel == 2) {
        #pragma unroll
        for (int mt = 0; mt < 4; mt++) {
            int rbase = row0 + wm * 64 + mt * 16 + qr;
            #pragma unroll
            for (int nt = 0; nt < 4; nt++) {
                int c = col0 + wn * 32 + nt * 8 + 2 * qc;
                int cc = c & 511;
                int h = cc >> 6, d = cc & 63;
                #pragma unroll
                for (int hh = 0; hh < 2; hh++) {
                    int r = rbase + hh * 8;
                    int b = r >> 9, n = r & 511;
                    float2 v = make_float2(acc[mt][nt][2*hh], acc[mt][nt][2*hh+1]);
                    *(float2*)(g_v + ((((size_t)b * NH + h) * NSEQ) + n) * DK + d) = v;
                }
            }
        }
    } else if (wsel == 1) {
        #pragma unroll
        for (int nt = 0; nt < 4; nt++) {
            int c = col0 + wn * 32 + nt * 8 + 2 * qc;
            int cc = c & 511;
            int h = cc >> 6, d0 = cc & 63;
            int ks = d0 >> 4, kk = d0 & 15, qcc = (kk >> 1) & 3, khalf = kk >> 3;
            #pragma unroll
            for (int mt = 0; mt < 4; mt++) {
                int rbase = row0 + wm * 64 + mt * 16 + qr;
                #pragma unroll
                for (int hh = 0; hh < 2; hh++) {
                    int r = rbase + hh * 8;
                    int b = r >> 9, n = r & 511;
                    int z = b * NH + h;
                    int jg = n >> 6, jl = n & 63;
                    int qrj = jl & 7, jhalf = (jl >> 3) & 1, mg = jl >> 4;
                    uint32_t* dst = reinterpret_cast<uint32_t*>(g_kfrag)
                                  + (size_t)(z*8 + jg)*4096;
                    int base = ((mg*4 + ks)*32 + qrj*4 + qcc)*4 + (jhalf + 2*khalf);
                    float vx = acc[mt][nt][2*hh], vy = acc[mt][nt][2*hh+1];
                    float h0 = bfhi(vx), h1 = bfhi(vy);
                    dst[base]        = pkbf2(h0, h1);
                    dst[2048 + base] = pkbf2(vx - h0, vy - h1);
                }
            }
        }
    } else {
        #pragma unroll
        for (int nt = 0; nt < 4; nt++) {
            int c = col0 + wn * 32 + nt * 8 + 2 * qc;
            int cc = c & 511;
            int h = cc >> 6, d0 = cc & 63;
            int ks = d0 >> 4, kk = d0 & 15, qcc = (kk >> 1) & 3, khalf = kk >> 3;
            float w0[5], w1[5];
            #pragma unroll
            for (int p = 0; p < 4; p++) {
                w0[p] = g_Mmat[d0*4 + p];
                w1[p] = g_Mmat[(d0+1)*4 + p];
            }
            w0[4] = g_cvec[d0];
            w1[4] = g_cvec[d0+1];
            #pragma unroll
            for (int mt = 0; mt < 4; mt++) {
                int rbase = row0 + wm * 64 + mt * 16 + qr;
                #pragma unroll
                for (int hh = 0; hh < 2; hh++) {
                    int r = rbase + hh * 8;
                    int b = r >> 9, n = r & 511;
                    int z = b * NH + h;
                    int ig = n >> 5, iin = n & 31;
                    int qri = iin & 7, ng = iin >> 3;
                    uint32_t* bd0 = reinterpret_cast<uint32_t*>(g_qfrag)
                                  + (size_t)(z*16 + ig)*5*2048;
                    int fb = ((ng*4 + ks)*32 + qri*4 + qcc)*4;
                    float vx = acc[mt][nt][2*hh], vy = acc[mt][nt][2*hh+1];
                    #pragma unroll
                    for (int ch = 0; ch < 5; ch++) {
                        float p0 = vx * w0[ch];
                        float p1 = vy * w1[ch];
                        float h0 = bfhi(p0), h1 = bfhi(p1);
                        uint32_t* bd = bd0 + ch*2048;
                        bd[fb + khalf]     = pkbf2(h0, h1);
                        bd[fb + 2 + khalf] = pkbf2(p0 - h0, p1 - h1);
                    }
                }
            }
        }
    }
}

// ============================================================================
// TF32 tensor-core GEMM (AV, fc, FFN1, FFN2) — proven R15 version.
// ============================================================================
template<int TN, int MAP, bool BTRANS, bool BIAS, bool RELU, bool RESID>
__global__ __launch_bounds__(256)
void tgemm_kernel(const float* __restrict__ A, const float* __restrict__ B0,
                  const float* __restrict__ bias, const float* __restrict__ resid,
                  float* __restrict__ C, int N, int K,
                  size_t strideA, size_t strideB)
{
    constexpr int NT   = TN / 32;
    constexpr int WN   = TN / 4;
    constexpr int BPAD = (TN == 128) ? 136 : 72;

    __shared__ __align__(16) float As[2][16][136];
    __shared__ __align__(16) float Bs[2][16][BPAD];

    int tid  = threadIdx.x;
    int lane = tid & 31, warp = tid >> 5;
    int wm = warp >> 2, wn = warp & 3;
    int qr = lane >> 2, qc = lane & 3;
    int row0 = blockIdx.y << 7;
    int col0 = blockIdx.x * TN;
    int z    = blockIdx.z;

    const float* Ab = A + (size_t)z * strideA;
    const float* Bb = BTRANS ? (B0 + (size_t)col0 * K)
                             : (B0 + (size_t)z * strideB + col0);

    int ar = tid >> 2, ak = (tid & 3) << 2;
    const float* Ald = Ab + (size_t)(row0 + ar) * K + ak;
    const float* Bld_t = Bb + (size_t)ar * K + ak;
    int bkr = tid >> 4, bn4 = (tid & 15) << 2;
    const float* Bld_n = Bb + (size_t)bkr * N + bn4;

    float acc[4][NT][4];
    #pragma unroll
    for (int mt = 0; mt < 4; mt++)
        #pragma unroll
        for (int nt = 0; nt < NT; nt++)
            #pragma unroll
            for (int c = 0; c < 4; c++) acc[mt][nt][c] = 0.f;

    float4 av[2], bv[2];
    auto ldG = [&](int k0) {
        av[0] = *(const float4*)(Ald + k0);
        av[1] = *(const float4*)(Ald + (size_t)64 * K + k0);
        if (BTRANS) {
            bv[0] = *(const float4*)(Bld_t + k0);
            if (TN == 128) bv[1] = *(const float4*)(Bld_t + (size_t)64 * K + k0);
        } else {
            bv[0] = *(const float4*)(Bld_n + (size_t)k0 * N);
        }
    };
    auto stS = [&](int buf) {
        #pragma unroll
        for (int h = 0; h < 2; h++) {
            int r = ar + h * 64;
            As[buf][ak+0][r] = to_tf32(((const float*)&av[h])[0]);
            As[buf][ak+1][r] = to_tf32(((const float*)&av[h])[1]);
            As[buf][ak+2][r] = to_tf32(((const float*)&av[h])[2]);
            As[buf][ak+3][r] = to_tf32(((const float*)&av[h])[3]);
        }
        if (BTRANS) {
            #pragma unroll
            for (int h = 0; h < (TN == 128 ? 2 : 1); h++) {
                int r = ar + h * 64;
                if (TN == 128 || r < TN) {
                    Bs[buf][ak+0][r] = to_tf32(((const float*)&bv[h])[0]);
                    Bs[buf][ak+1][r] = to_tf32(((const float*)&bv[h])[1]);
                    Bs[buf][ak+2][r] = to_tf32(((const float*)&bv[h])[2]);
                    Bs[buf][ak+3][r] = to_tf32(((const float*)&bv[h])[3]);
                }
            }
        } else {
            float4 t = make_float4(to_tf32(bv[0].x), to_tf32(bv[0].y),
                                   to_tf32(bv[0].z), to_tf32(bv[0].w));
            *(float4*)&Bs[buf][bkr][bn4] = t;
        }
    };
    auto compute = [&](int buf) {
        #pragma unroll
        for (int ks = 0; ks < 2; ks++) {
            int kb = ks * 8;
            uint32_t af[4][4], bf[NT][2];
            #pragma unroll
            for (int mt = 0; mt < 4; mt++) {
                int mb = wm * 64 + mt * 16;
                af[mt][0] = __float_as_uint(As[buf][kb+qc  ][mb+qr  ]);
                af[mt][1] = __float_as_uint(As[buf][kb+qc  ][mb+qr+8]);
                af[mt][2] = __float_as_uint(As[buf][kb+qc+4][mb+qr  ]);
                af[mt][3] = __float_as_uint(As[buf][kb+qc+4][mb+qr+8]);
            }
            #pragma unroll
            for (int nt = 0; nt < NT; nt++) {
                int nb = wn * WN + nt * 8;
                bf[nt][0] = __float_as_uint(Bs[buf][kb+qc  ][nb+qr]);
                bf[nt][1] = __float_as_uint(Bs[buf][kb+qc+4][nb+qr]);
            }
            #pragma unroll
            for (int mt = 0; mt < 4; mt++)
                #pragma unroll
                for (int nt = 0; nt < NT; nt++)
                    mma_tf32(acc[mt][nt], af[mt], bf[nt]);
        }
    };

    ldG(0);
    stS(0);
    __syncthreads();
    int buf = 0;
    for (int k0 = 16; k0 < K; k0 += 16) {
        ldG(k0);
        compute(buf);
        stS(buf ^ 1);
        __syncthreads();
        buf ^= 1;
    }
    compute(buf);

    #pragma unroll
    for (int mt = 0; mt < 4; mt++) {
        int rbase = row0 + wm * 64 + mt * 16 + qr;
        #pragma unroll
        for (int nt = 0; nt < NT; nt++) {
            int cg = col0 + wn * WN + nt * 8 + 2 * qc;
            #pragma unroll
            for (int hh = 0; hh < 2; hh++) {
                int r = rbase + hh * 8;
                float2 v = make_float2(acc[mt][nt][2*hh], acc[mt][nt][2*hh+1]);
                if (BIAS) { v.x += bias[cg]; v.y += bias[cg+1]; }
                if (RESID) {
                    const float2 rz = *(const float2*)(resid + (size_t)r * N + cg);
                    v.x += rz.x; v.y += rz.y;
                }
                if (RELU) { v.x = fmaxf(v.x, 0.f); v.y = fmaxf(v.y, 0.f); }
                if (MAP == 0) {
                    *(float2*)(C + (size_t)r * N + cg) = v;
                } else {
                    int b = z >> 3, h2 = z & 7;
                    *(float2*)(g_heads + ((size_t)(b * NSEQ) + r) * DMODEL + h2 * DK + cg) = v;
                }
            }
        }
    }
}

// ============================================================================
// scores v6: all 8 heads per block (pos in registers); bf16 3-term m16n8k16.
// ============================================================================
__global__ __launch_bounds__(256)
void scores_tc_kernel(const float* __restrict__ pos, float* __restrict__ attn)
{
    int tid  = threadIdx.x;
    int lane = tid & 31, warp = tid >> 5;
    int wm = warp >> 2, wn = warp & 3;
    int qr = lane >> 2, qc = lane & 3;
    int ig = blockIdx.x, jg = blockIdx.y, bbx = blockIdx.z;
    int i0 = ig << 5, j0 = jg << 6;
    int colb = i0 + wn*8 + 2*qc;

    float4 pr[2][2][2];
    #pragma unroll
    for (int mt = 0; mt < 2; mt++)
        #pragma unroll
        for (int hf = 0; hf < 2; hf++) {
            int row = j0 + wm*32 + mt*16 + qr + 8*hf;
            const float* pp = pos + (((size_t)(bbx*NSEQ + row))*NSEQ + colb)*4;
            pr[mt][hf][0] = *(const float4*)pp;
            pr[mt][hf][1] = *(const float4*)(pp + 4);
        }

    #pragma unroll 1
    for (int h = 0; h < NH; h++) {
        int z = bbx*NH + h;
        const uint4* Af = g_kfrag + (size_t)(z*8 + jg)*1024;
        const uint4* Bf = g_qfrag + (size_t)(z*16 + ig)*2560 + wn*128 + lane;

        float acc[5][2][4];
        #pragma unroll
        for (int ch = 0; ch < 5; ch++)
            #pragma unroll
            for (int mt = 0; mt < 2; mt++)
                #pragma unroll
                for (int c = 0; c < 4; c++) acc[ch][mt][c] = 0.f;

        #pragma unroll
        for (int ks = 0; ks < 4; ks++) {
            uint4 ah[2], al[2];
            #pragma unroll
            for (int mt = 0; mt < 2; mt++) {
                int fi = (wm*2 + mt)*128 + ks*32 + lane;
                ah[mt] = __ldg(&Af[fi]);
                al[mt] = __ldg(&Af[512 + fi]);
            }
            #pragma unroll
            for (int ch = 0; ch < 5; ch++) {
                uint4 bq = __ldg(&Bf[ch*512 + ks*32]);
                #pragma unroll
                for (int mt = 0; mt < 2; mt++) {
                    mma_bf16(acc[ch][mt], ah[mt], bq.x, bq.y);
                    mma_bf16(acc[ch][mt], ah[mt], bq.z, bq.w);
                    mma_bf16(acc[ch][mt], al[mt], bq.x, bq.y);
                }
            }
        }

        #pragma unroll
        for (int mt = 0; mt < 2; mt++)
            #pragma unroll
            for (int hf = 0; hf < 2; hf++) {
                int row = j0 + wm*32 + mt*16 + qr + 8*hf;
                float4 p0 = pr[mt][hf][0];
                float4 p1 = pr[mt][hf][1];
                int c = 2*hf;
                float s0 = acc[4][mt][c]
                         + p0.x*acc[0][mt][c] + p0.y*acc[1][mt][c]
                         + p0.z*acc[2][mt][c] + p0.w*acc[3][mt][c];
                float s1 = acc[4][mt][c+1]
                         + p1.x*acc[0][mt][c+1] + p1.y*acc[1][mt][c+1]
                         + p1.z*acc[2][mt][c+1] + p1.w*acc[3][mt][c+1];
                *(float2*)(attn + ((size_t)z*NSEQ + row)*NSEQ + colb) =
                    make_float2(s0*INV_T, s1*INV_T);
            }
    }
}

// ---------------- softmax: warp per row, 8 rows per block, float4 -----------
__global__ __launch_bounds__(256)
void softmax_kernel(float* __restrict__ attn)
{
    int warp = threadIdx.x >> 5, lane = threadIdx.x & 31;
    size_t row = (size_t)blockIdx.x * 8 + warp;
    float4* p = reinterpret_cast<float4*>(attn + row * NSEQ);

    float4 v[4];
    #pragma unroll
    for (int u = 0; u < 4; u++) v[u] = p[lane + 32*u];

    float m = -1e30f;
    #pragma unroll
    for (int u = 0; u < 4; u++)
        m = fmaxf(m, fmaxf(fmaxf(v[u].x, v[u].y), fmaxf(v[u].z, v[u].w)));
    m = warp_max(m);

    float s = 0.f;
    #pragma unroll
    for (int u = 0; u < 4; u++) {
        v[u].x = __expf(v[u].x - m); v[u].y = __expf(v[u].y - m);
        v[u].z = __expf(v[u].z - m); v[u].w = __expf(v[u].w - m);
        s += v[u].x + v[u].y + v[u].z + v[u].w;
    }
    s = warp_sum(s);
    float inv = 1.0f / s;
    #pragma unroll
    for (int u = 0; u < 4; u++) {
        v[u].x *= inv; v[u].y *= inv; v[u].z *= inv; v[u].w *= inv;
        p[lane + 32*u] = v[u];
    }
}

// ---------------- layer norm (one token per block) ---------------------------
__global__ __launch_bounds__(256)
void layernorm_kernel(const float* __restrict__ x, const float* __restrict__ gam,
                      const float* __restrict__ bet, float* __restrict__ out)
{
    int t = blockIdx.x, tid = threadIdx.x;
    const float* xr = x + (size_t)t * DMODEL;
    __shared__ float red[8];

    float a0 = xr[tid], a1 = xr[tid + 256];
    float s = warp_sum(a0 + a1);
    if ((tid & 31) == 0) red[tid >> 5] = s;
    __syncthreads();
    s = red[0];
    #pragma unroll
    for (int w = 1; w < 8; w++) s += red[w];
    float mu = s * (1.0f / DMODEL);
    float d0 = a0 - mu, d1 = a1 - mu;
    __syncthreads();

    float q = warp_sum(d0*d0 + d1*d1);
    if ((tid & 31) == 0) red[tid >> 5] = q;
    __syncthreads();
    q = red[0];
    #pragma unroll
    for (int w = 1; w < 8; w++) q += red[w];
    float inv = rsqrtf(q * (1.0f / DMODEL) + LN_EPS);

    float* orow = out + (size_t)t * DMODEL;
    orow[tid]       = d0 * inv * gam[tid]       + bet[tid];
    orow[tid + 256] = d1 * inv * gam[tid + 256] + bet[tid + 256];
}

// ---------------- launch -----------------------------------------------------
extern "C" void kernel_launch(void* const* d_in, const int* in_sizes, int n_in,
                              void* d_out, int out_size)
{
    (void)in_sizes; (void)n_in; (void)out_size;
    const float* enc    = (const float*)d_in[0];
    const float* pos    = (const float*)d_in[1];
    const float* w_qs   = (const float*)d_in[2];
    const float* w_ks   = (const float*)d_in[3];
    const float* w_vs   = (const float*)d_in[4];
    const float* w_fc   = (const float*)d_in[5];
    const float* rp_w1  = (const float*)d_in[6];
    const float* rp_b1  = (const float*)d_in[7];
    const float* rp_w2  = (const float*)d_in[8];
    const float* rp_b2  = (const float*)d_in[9];
    const float* ln1_g  = (const float*)d_in[10];
    const float* ln1_b  = (const float*)d_in[11];
    const float* ln2_g  = (const float*)d_in[12];
    const float* ln2_b  = (const float*)d_in[13];
    const float* ffn_w1 = (const float*)d_in[14];
    const float* ffn_b1 = (const float*)d_in[15];
    const float* ffn_w2 = (const float*)d_in[16];
    const float* ffn_b2 = (const float*)d_in[17];

    float* out2 = (float*)d_out;                          // [4,512,512]
    float* attn = out2 + (size_t)TOK * DMODEL;            // [4,8,512,512]

    float *pv, *pheads, *ptmp1, *pln1, *pffh, *ptmp2;
    cudaGetSymbolAddress((void**)&pv,     g_v);
    cudaGetSymbolAddress((void**)&pheads, g_heads);
    cudaGetSymbolAddress((void**)&ptmp1,  g_tmp1);
    cudaGetSymbolAddress((void**)&pln1,   g_ln1);
    cudaGetSymbolAddress((void**)&pffh,   g_ffh);
    cudaGetSymbolAddress((void**)&ptmp2,  g_tmp2);

    // 1) collapse rel-pos MLP
    rp_combine_kernel<<<1, 64>>>(rp_w1, rp_b1, rp_w2, rp_b2);

    // 2+3) QKV projection; epilogue writes scores fragments (no prep kernel)
    {
        dim3 g(6, TOK/128, 1);
        qkv3_kernel<<<g, 256>>>(enc, w_qs, w_ks, w_vs, 0);
        qkv3_kernel<<<g, 256>>>(enc, w_qs, w_ks, w_vs, 768);
    }

    // 4) relative-position attention logits (slot 4 -> profiled)
    {
        dim3 g(NSEQ/32, NSEQ/64, BB);      // 512 blocks
        scores_tc_kernel<<<g, 256>>>(pos, attn);
    }

    // 5) softmax in place (warp per row)
    softmax_kernel<<<BB*NH*NSEQ/8, 256>>>(attn);

    // 6) AV (tf32): per (b,h): P @ V -> g_heads
    {
        dim3 g(1, NSEQ/128, BB*NH);
        tgemm_kernel<64, 2, false, false, false, false><<<g, 256>>>(
            attn, pv, nullptr, nullptr, nullptr,
            DK, NSEQ, (size_t)NSEQ*NSEQ, (size_t)NSEQ*DK);
    }

    // 7) fc + residual(enc) -> g_tmp1 ; LN1
    {
        dim3 g(DMODEL/64, TOK/128, 1);
        tgemm_kernel<64, 0, true, false, false, true><<<g, 256>>>(
            pheads, w_fc, nullptr, enc, ptmp1, DMODEL, DMODEL, 0, 0);
    }
    layernorm_kernel<<<TOK, 256>>>(ptmp1, ln1_g, ln1_b, pln1);

    // 8) FFN1: relu(ln1 @ W1^T + b1) -> g_ffh
    {
        dim3 g(DINNER/128, TOK/128, 1);
        tgemm_kernel<128, 0, true, true, true, false><<<g, 256>>>(
            pln1, ffn_w1, ffn_b1, nullptr, pffh, DINNER, DMODEL, 0, 0);
    }

    // 9) FFN2: ffh @ W2^T + b2 + ln1 -> g_tmp2
    {
        dim3 g(DMODEL/64, TOK/128, 1);
        tgemm_kernel<64, 0, true, true, false, true><<<g, 256>>>(
            pffh, ffn_w2, ffn_b2, pln1, ptmp2, DMODEL, DINNER, 0, 0);
    }

    // 10) LN2 -> out2
    layernorm_kernel<<<TOK, 256>>>(ptmp2, ln2_g, ln2_b, out2);
}